// round 1
// baseline (speedup 1.0000x reference)
#include <cuda_runtime.h>
#include <float.h>

// ChamferDist: loss = mean_b( w_b * mean_k( min_j ||adv[b,k]-ori[b,j]||^2 ) )
//
// Strategy: min_j(a2 + b2_j - 2 a.b_j) = a2 + min_j(b2_j - 2 a.b_j).
// Per batch, precompute (-2ox, -2oy, -2oz, ||o||^2) as float4 in smem.
// Inner loop per (adv point, ori point): 3 FFMA + 1 FMNMX + 1/4 LDS.128.
// 256 threads/CTA, 1 adv point per thread -> B*K/256 = 128 CTAs (one wave).
// Deterministic two-stage reduction via __device__ scratch (no float atomics).

#define CD_THREADS 256
#define CD_MAX_BLOCKS 8192

__device__ float g_cd_partial[CD_MAX_BLOCKS];

__global__ __launch_bounds__(CD_THREADS)
void chamfer_main_kernel(const float* __restrict__ adv,
                         const float* __restrict__ ori,
                         const float* __restrict__ w,
                         int K, int tilesPerBatch) {
    extern __shared__ float4 s_ori[];  // K float4 entries

    const int tile = blockIdx.x % tilesPerBatch;
    const int b    = blockIdx.x / tilesPerBatch;

    // Cooperative load + transform of this batch's ori points into smem.
    const float* __restrict__ orib = ori + (size_t)b * K * 3;
    for (int j = threadIdx.x; j < K; j += CD_THREADS) {
        float x = orib[3 * j + 0];
        float y = orib[3 * j + 1];
        float z = orib[3 * j + 2];
        s_ori[j] = make_float4(-2.0f * x, -2.0f * y, -2.0f * z,
                               x * x + y * y + z * z);
    }
    __syncthreads();

    const int k = tile * CD_THREADS + threadIdx.x;
    float local = 0.0f;
    if (k < K) {
        const float* __restrict__ a = adv + ((size_t)b * K + k) * 3;
        const float ax = a[0], ay = a[1], az = a[2];
        float m = FLT_MAX;
#pragma unroll 4
        for (int j = 0; j < K; ++j) {
            float4 o = s_ori[j];
            float t = fmaf(az, o.z, o.w);
            t = fmaf(ay, o.y, t);
            t = fmaf(ax, o.x, t);
            m = fminf(m, t);
        }
        local = m + (ax * ax + ay * ay + az * az);
    }

    // Block-level deterministic sum reduction.
    __shared__ float red[CD_THREADS / 32];
    const int lane = threadIdx.x & 31;
    const int wid  = threadIdx.x >> 5;
#pragma unroll
    for (int off = 16; off > 0; off >>= 1)
        local += __shfl_down_sync(0xffffffffu, local, off);
    if (lane == 0) red[wid] = local;
    __syncthreads();
    if (threadIdx.x == 0) {
        float v = 0.0f;
#pragma unroll
        for (int i = 0; i < CD_THREADS / 32; ++i) v += red[i];
        g_cd_partial[blockIdx.x] = v * w[b];
    }
}

__global__ void chamfer_finalize_kernel(float* __restrict__ out,
                                        int nblocks, float scale) {
    float s = 0.0f;
    for (int i = threadIdx.x; i < nblocks; i += 32)
        s += g_cd_partial[i];
#pragma unroll
    for (int off = 16; off > 0; off >>= 1)
        s += __shfl_down_sync(0xffffffffu, s, off);
    if (threadIdx.x == 0) out[0] = s * scale;
}

extern "C" void kernel_launch(void* const* d_in, const int* in_sizes, int n_in,
                              void* d_out, int out_size) {
    const float* adv = (const float*)d_in[0];   // [B, K, 3] float32
    const float* ori = (const float*)d_in[1];   // [B, K, 3] float32
    const float* w   = (const float*)d_in[2];   // [B]       float32
    float* out = (float*)d_out;                 // scalar float32

    const int B = in_sizes[2];
    const int K = in_sizes[0] / (3 * B);

    const int tilesPerBatch = (K + CD_THREADS - 1) / CD_THREADS;
    const int blocks = B * tilesPerBatch;

    const size_t smem = (size_t)K * sizeof(float4);
    cudaFuncSetAttribute(chamfer_main_kernel,
                         cudaFuncAttributeMaxDynamicSharedMemorySize,
                         (int)smem);

    chamfer_main_kernel<<<blocks, CD_THREADS, smem>>>(adv, ori, w, K,
                                                      tilesPerBatch);
    const float scale = 1.0f / ((float)B * (float)K);
    chamfer_finalize_kernel<<<1, 32>>>(out, blocks, scale);
}